// round 6
// baseline (speedup 1.0000x reference)
#include <cuda_runtime.h>
#include <cstdint>
#include <math.h>

#define GAMMA 3.4f
#define EPS 1e-8f
#define B_DIM 2048
#define P_TOK 197
#define P_USE 196
#define D_DIM 768
#define NWARP 7
#define NTHREADS (NWARP * 32)      // 224
#define PPW (P_USE / NWARP)        // 28 patches per warp
#define ROW_BYTES (D_DIM * 4)      // 3072
#define DEPTH 2

__device__ double g_acc;           // zero-initialized
__device__ unsigned int g_count;

__global__ __launch_bounds__(NTHREADS) void loss_fused_kernel(
    const float* __restrict__ patch_tokens,
    const float* __restrict__ out_text,
    const float* __restrict__ gt,
    float* __restrict__ out)
{
    __shared__ float4 s_ot[D_DIM / 4];                       // 3 KB
    __shared__ float  s_gt[P_USE];
    __shared__ float  s_otn;
    __shared__ float  warp_sum[NWARP];
    __shared__ __align__(16) char s_buf[NWARP * DEPTH * ROW_BYTES];   // 42 KB

    const int b    = blockIdx.x;
    const int tid  = threadIdx.x;
    const int warp = tid >> 5;
    const int lane = tid & 31;

    // Stage out_text[b] and gt[b] into smem (coalesced).
    const float4* ot4 = reinterpret_cast<const float4*>(out_text + (size_t)b * D_DIM);
    if (tid < D_DIM / 4) s_ot[tid] = __ldg(&ot4[tid]);
    if (tid < P_USE) s_gt[tid] = __ldg(&gt[(size_t)b * P_USE + tid]);
    __syncthreads();

    if (warp == 0) {
        float otn2 = 0.f;
#pragma unroll
        for (int j = 0; j < 6; ++j) {
            float4 q = s_ot[lane + 32 * j];
            otn2 += q.x * q.x + q.y * q.y + q.z * q.z + q.w * q.w;
        }
#pragma unroll
        for (int off = 16; off > 0; off >>= 1)
            otn2 += __shfl_xor_sync(0xffffffffu, otn2, off);
        if (lane == 0) s_otn = fmaxf(sqrtf(otn2), EPS);
    }
    __syncthreads();
    const float ot_n = s_otn;

    const int p0 = warp * PPW;
    const float* batch_base = patch_tokens + (size_t)b * P_TOK * D_DIM;

    // Warp-private double buffer. Lane j-th chunk: offset lane*16 + j*512,
    // mirroring gmem (lane + 32*j)*16 — each lane reads back only its own
    // copies, so no intra-warp sync is needed in the loop.
    const uint32_t buf_base = (uint32_t)__cvta_generic_to_shared(s_buf)
                            + warp * (DEPTH * ROW_BYTES);

    auto stage_row = [&](int p, int slot) {
        const char* src = reinterpret_cast<const char*>(
            batch_base + (size_t)(p + 1) * D_DIM) + lane * 16;
        uint32_t dst = buf_base + slot * ROW_BYTES + lane * 16;
#pragma unroll
        for (int j = 0; j < 6; ++j) {
            asm volatile("cp.async.cg.shared.global [%0], [%1], 16;\n"
                         :: "r"(dst + j * 512), "l"(src + j * 512));
        }
        asm volatile("cp.async.commit_group;\n");
    };

    // Prologue: rows p0, p0+1 in flight.
    stage_row(p0, 0);
    stage_row(p0 + 1, 1);

    float local = 0.f;

    for (int i = 0; i < PPW; ++i) {
        const int p = p0 + i;
        // Wait until at most 1 group outstanding -> row i landed.
        asm volatile("cp.async.wait_group 1;\n");

        const int slot = i & 1;
        const char* rb = s_buf + warp * (DEPTH * ROW_BYTES) + slot * ROW_BYTES + lane * 16;

        float dot = 0.f, nn = 0.f;
#pragma unroll
        for (int j = 0; j < 6; ++j) {
            float4 v = *reinterpret_cast<const float4*>(rb + j * 512);
            float4 q = s_ot[lane + 32 * j];
            dot += v.x * q.x + v.y * q.y + v.z * q.z + v.w * q.w;
            nn  += v.x * v.x + v.y * v.y + v.z * v.z + v.w * v.w;
        }

        // Refill this slot immediately (lane has consumed its own bytes).
        if (i + 2 < PPW) stage_row(p + 2, slot);
        else asm volatile("cp.async.commit_group;\n");  // keep group count in step

#pragma unroll
        for (int off = 16; off > 0; off >>= 1) {
            dot += __shfl_xor_sync(0xffffffffu, dot, off);
            nn  += __shfl_xor_sync(0xffffffffu, nn,  off);
        }

        if (lane == 0) {
            const float pt_n = fmaxf(sqrtf(nn), EPS);
            const float cosv = dot / (pt_n * ot_n);
            const float vec  = 1.0f / (1.0f + expf(cosv - 1.0f));   // sigmoid(1-cos)
            const float gtv  = s_gt[p] * (1.0f / 255.0f);
            const float diff = fabsf(vec - gtv);
            local += -logf(1.0f - diff) * (gtv * GAMMA + 1.0f);
        }
    }
    asm volatile("cp.async.wait_group 0;\n");

    if (lane == 0) warp_sum[warp] = local;
    __syncthreads();

    if (tid == 0) {
        float s = 0.f;
#pragma unroll
        for (int w = 0; w < NWARP; ++w) s += warp_sum[w];
        atomicAdd(&g_acc, (double)s);

        __threadfence();
        unsigned int arrived = atomicAdd(&g_count, 1u);
        if (arrived == B_DIM - 1) {
            double total = atomicAdd(&g_acc, 0.0);
            out[0] = (float)(total / (double)B_DIM);
            g_acc = 0.0;
            g_count = 0u;
        }
    }
}

extern "C" void kernel_launch(void* const* d_in, const int* in_sizes, int n_in,
                              void* d_out, int out_size) {
    const float* patch_tokens = (const float*)d_in[0];
    const float* out_text     = (const float*)d_in[1];
    const float* gt           = (const float*)d_in[2];
    float* out = (float*)d_out;

    loss_fused_kernel<<<B_DIM, NTHREADS>>>(patch_tokens, out_text, gt, out);
}

// round 7
// speedup vs baseline: 1.1496x; 1.1496x over previous
#include <cuda_runtime.h>
#include <math.h>

#define GAMMA 3.4f
#define EPS 1e-8f
#define B_DIM 2048
#define P_TOK 197
#define P_USE 196
#define D_DIM 768
#define NWARP 7
#define NTHREADS (NWARP * 32)      // 224
#define NSPLIT 2                   // blocks per batch
#define PPB (P_USE / NSPLIT)       // 98 patches per block
#define PPW (PPB / NWARP)          // 14 patches per warp
#define NBLOCKS (B_DIM * NSPLIT)   // 4096

__device__ double g_acc;           // zero-initialized
__device__ unsigned int g_count;

__global__ __launch_bounds__(NTHREADS, 4) void loss_fused_kernel(
    const float* __restrict__ patch_tokens,
    const float* __restrict__ out_text,
    const float* __restrict__ gt,
    float* __restrict__ out)
{
    __shared__ float4 s_ot[D_DIM / 4];    // 3 KB
    __shared__ float  s_gt[PPB];
    __shared__ float  s_otn;
    __shared__ float  warp_sum[NWARP];

    const int b    = blockIdx.x;
    const int half = blockIdx.y;           // 0 or 1
    const int tid  = threadIdx.x;
    const int warp = tid >> 5;
    const int lane = tid & 31;
    const int pbase = half * PPB;

    // Stage out_text[b] and this half's gt slice into smem (coalesced).
    const float4* ot4 = reinterpret_cast<const float4*>(out_text + (size_t)b * D_DIM);
    if (tid < D_DIM / 4) s_ot[tid] = __ldg(&ot4[tid]);
    if (tid < PPB) s_gt[tid] = __ldg(&gt[(size_t)b * P_USE + pbase + tid]);
    __syncthreads();

    if (warp == 0) {
        float otn2 = 0.f;
#pragma unroll
        for (int j = 0; j < 6; ++j) {
            float4 q = s_ot[lane + 32 * j];
            otn2 += q.x * q.x + q.y * q.y + q.z * q.z + q.w * q.w;
        }
#pragma unroll
        for (int off = 16; off > 0; off >>= 1)
            otn2 += __shfl_xor_sync(0xffffffffu, otn2, off);
        if (lane == 0) s_otn = fmaxf(sqrtf(otn2), EPS);
    }
    __syncthreads();
    const float ot_n = s_otn;

    float local = 0.f;
    const int p0 = pbase + warp * PPW;

    // Register double-buffer: next row's 6 loads in flight while reducing
    // the current row, so HBM never idles during the SHFL chain.
    const float4* row0 = reinterpret_cast<const float4*>(
        patch_tokens + ((size_t)b * P_TOK + (size_t)(p0 + 1)) * D_DIM);
    float4 v[6];
#pragma unroll
    for (int j = 0; j < 6; ++j) v[j] = __ldcs(&row0[lane + 32 * j]);

    for (int i = 0; i < PPW; ++i) {
        const int p = p0 + i;

        float4 w[6];
        if (i + 1 < PPW) {
            const float4* rown = reinterpret_cast<const float4*>(
                patch_tokens + ((size_t)b * P_TOK + (size_t)(p + 2)) * D_DIM);
#pragma unroll
            for (int j = 0; j < 6; ++j) w[j] = __ldcs(&rown[lane + 32 * j]);
        }

        float dot = 0.f, nn = 0.f;
#pragma unroll
        for (int j = 0; j < 6; ++j) {
            float4 q = s_ot[lane + 32 * j];
            dot += v[j].x * q.x + v[j].y * q.y + v[j].z * q.z + v[j].w * q.w;
            nn  += v[j].x * v[j].x + v[j].y * v[j].y + v[j].z * v[j].z + v[j].w * v[j].w;
        }
#pragma unroll
        for (int off = 16; off > 0; off >>= 1) {
            dot += __shfl_xor_sync(0xffffffffu, dot, off);
            nn  += __shfl_xor_sync(0xffffffffu, nn,  off);
        }

        if (lane == 0) {
            const float pt_n = fmaxf(sqrtf(nn), EPS);
            const float cosv = dot / (pt_n * ot_n);
            const float vec  = 1.0f / (1.0f + expf(cosv - 1.0f));   // sigmoid(1-cos)
            const float gtv  = s_gt[p - pbase] * (1.0f / 255.0f);
            const float diff = fabsf(vec - gtv);
            local += -logf(1.0f - diff) * (gtv * GAMMA + 1.0f);
        }

#pragma unroll
        for (int j = 0; j < 6; ++j) v[j] = w[j];
    }

    if (lane == 0) warp_sum[warp] = local;
    __syncthreads();

    if (tid == 0) {
        float s = 0.f;
#pragma unroll
        for (int w2 = 0; w2 < NWARP; ++w2) s += warp_sum[w2];
        atomicAdd(&g_acc, (double)s);

        __threadfence();
        unsigned int arrived = atomicAdd(&g_count, 1u);
        if (arrived == NBLOCKS - 1) {
            double total = atomicAdd(&g_acc, 0.0);
            out[0] = (float)(total / (double)B_DIM);
            g_acc = 0.0;
            g_count = 0u;
        }
    }
}

extern "C" void kernel_launch(void* const* d_in, const int* in_sizes, int n_in,
                              void* d_out, int out_size) {
    const float* patch_tokens = (const float*)d_in[0];
    const float* out_text     = (const float*)d_in[1];
    const float* gt           = (const float*)d_in[2];
    float* out = (float*)d_out;

    dim3 grid(B_DIM, NSPLIT);   // 2048 x 2
    loss_fused_kernel<<<grid, NTHREADS>>>(patch_tokens, out_text, gt, out);
}